// round 5
// baseline (speedup 1.0000x reference)
#include <cuda_runtime.h>
#include <cuda_bf16.h>
#include <cstdint>

#define B_  1024
#define N_  128
#define H_  128
#define FE_ 8
#define G3_ 384
#define KX_ 136
#define KP_ 152          // padded K stride in elements (304 bytes)
#define KSTEPS 9         // K = 144 (128 h + 8 jets + 8 zero)

// ---------------- device scratch ----------------
__device__ __align__(16) float g_hs[B_ * H_];
__device__ __align__(16) float g_bias[B_ * G3_];
__device__ __align__(16) __nv_bfloat16 g_Bhi[G3_ * KP_];
__device__ __align__(16) __nv_bfloat16 g_Blo[G3_ * KP_];

__device__ __forceinline__ uint32_t pack_bf2(float a, float b) {
    __nv_bfloat16 ah = __float2bfloat16(a), bh = __float2bfloat16(b);
    return (uint32_t)__bfloat16_as_ushort(ah) | ((uint32_t)__bfloat16_as_ushort(bh) << 16);
}
__device__ __forceinline__ uint32_t pack_bf2_res(float a, float b) {
    __nv_bfloat16 ah = __float2bfloat16(a), bh = __float2bfloat16(b);
    float ar = a - __bfloat162float(ah), br = b - __bfloat162float(bh);
    return (uint32_t)__bfloat16_as_ushort(__float2bfloat16(ar))
         | ((uint32_t)__bfloat16_as_ushort(__float2bfloat16(br)) << 16);
}
__device__ __forceinline__ float bf_lo(uint32_t u) {
    return __bfloat162float(__ushort_as_bfloat16((unsigned short)(u & 0xffff)));
}
__device__ __forceinline__ float bf_hi(uint32_t u) {
    return __bfloat162float(__ushort_as_bfloat16((unsigned short)(u >> 16)));
}
__device__ __forceinline__ uint32_t smem_u32(const void* p) {
    uint32_t a;
    asm("{ .reg .u64 t; cvta.to.shared.u64 t, %1; cvt.u32.u64 %0, t; }" : "=r"(a) : "l"(p));
    return a;
}
__device__ __forceinline__ void ldm_x4(uint32_t* r, uint32_t addr) {
    asm volatile("ldmatrix.sync.aligned.m8n8.x4.shared.b16 {%0,%1,%2,%3}, [%4];"
                 : "=r"(r[0]), "=r"(r[1]), "=r"(r[2]), "=r"(r[3]) : "r"(addr));
}

#define MMA16816(ac, a0, a1, a2, a3, b0, b1)                                   \
    asm volatile("mma.sync.aligned.m16n8k16.row.col.f32.bf16.bf16.f32 "        \
                 "{%0,%1,%2,%3}, {%4,%5,%6,%7}, {%8,%9}, {%0,%1,%2,%3};"       \
                 : "+f"((ac)[0]), "+f"((ac)[1]), "+f"((ac)[2]), "+f"((ac)[3])  \
                 : "r"(a0), "r"(a1), "r"(a2), "r"(a3), "r"(b0), "r"(b1))

// ---------------- prep: W_hh (+jets cols of W_ih for r,z) -> bf16 hi/lo ----------------
__global__ void k_prep(const float* __restrict__ Whh, const float* __restrict__ Wih) {
    int i = blockIdx.x * 256 + threadIdx.x;
    if (i >= G3_ * KP_) return;
    int g = i / KP_, k = i % KP_;
    float w = 0.f;
    if (k < H_) w = Whh[g * H_ + k];
    else if (k < H_ + FE_ && g < 2 * H_) w = Wih[(size_t)g * KX_ + k];
    __nv_bfloat16 hi = __float2bfloat16(w);
    g_Bhi[i] = hi;
    g_Blo[i] = __float2bfloat16(w - __bfloat162float(hi));
}

// ---------------- rowsum ----------------
__global__ void k_rowsum(const float* __restrict__ h) {
    __shared__ float4 red[256];
    int b = blockIdx.x, tid = threadIdx.x;
    int k4 = tid & 31, n0 = tid >> 5;
    const float4* p = (const float4*)(h + (size_t)b * N_ * H_) + k4;
    float4 s = make_float4(0.f, 0.f, 0.f, 0.f);
    #pragma unroll
    for (int j = 0; j < 16; j++) {
        float4 v = p[(size_t)(n0 + 8 * j) * 32];
        s.x += v.x; s.y += v.y; s.z += v.z; s.w += v.w;
    }
    red[tid] = s;
    __syncthreads();
    #pragma unroll
    for (int off = 128; off >= 32; off >>= 1) {
        if (tid < off) {
            float4 a = red[tid], c = red[tid + off];
            a.x += c.x; a.y += c.y; a.z += c.z; a.w += c.w;
            red[tid] = a;
        }
        __syncthreads();
    }
    if (tid < 32) ((float4*)g_hs)[b * 32 + tid] = red[tid];
}

// ---------------- bias ----------------
__global__ void k_bias(const float* __restrict__ Wm, const float* __restrict__ bm,
                       const float* __restrict__ Wih, const float* __restrict__ bih,
                       const float* __restrict__ bhh) {
    __shared__ float hsS[H_];
    __shared__ float msgS[H_];
    int b = blockIdx.x;
    int k = threadIdx.x;
    hsS[k] = g_hs[b * H_ + k];
    __syncthreads();
    const float4* wr = (const float4*)(Wm + (size_t)k * H_);
    float d = 0.f;
    #pragma unroll
    for (int j = 0; j < H_ / 4; j++) {
        float4 w = wr[j];
        d += hsS[4 * j + 0] * w.x + hsS[4 * j + 1] * w.y
           + hsS[4 * j + 2] * w.z + hsS[4 * j + 3] * w.w;
    }
    msgS[k] = tanhf(d + (float)N_ * bm[k]);
    __syncthreads();
    #pragma unroll
    for (int q = 0; q < 3; q++) {
        int g = q * H_ + k;
        const float4* wi = (const float4*)(Wih + (size_t)g * KX_);
        float d2 = 0.f;
        #pragma unroll
        for (int j = 0; j < H_ / 4; j++) {
            float4 w = wi[j];
            d2 += msgS[4 * j + 0] * w.x + msgS[4 * j + 1] * w.y
                + msgS[4 * j + 2] * w.z + msgS[4 * j + 3] * w.w;
        }
        float bias = d2 + bih[g];
        if (g < 2 * H_) bias += bhh[g];
        g_bias[b * G3_ + g] = bias;
    }
}

// ---------------- smem layout (bytes) ----------------
#define OFF_B    0            // 116736  B [384][152] bf16 (hi, reloaded as lo)
#define OFF_AH   116736       //  38912  A_hi [128][152] bf16
#define OFF_AL   155648       //  38912
#define OFF_JET  194560       //   4096  jets fp32 [128][8]
#define OFF_WJN  198656       //   4096  W_ih n-gate jets cols fp32 [128][8]
#define OFF_BIAS 202752       //   1536
#define OFF_BHHN 204288       //    512
#define SMEM_SZ  204800

// ---------------- main ----------------
__global__ void __launch_bounds__(256, 1) k_main(
    const float* __restrict__ h, const float* __restrict__ jets,
    const float* __restrict__ Wih, const float* __restrict__ bhh,
    float* __restrict__ out)
{
    extern __shared__ char smem[];
    const int tid  = threadIdx.x;
    const int wid  = tid >> 5;
    const int lane = tid & 31;
    const int cta  = blockIdx.x;
    const int wm   = wid & 1;        // 0..1 : M half (64 rows)
    const int wn   = wid >> 1;       // 0..3 : 32 gate-cols per gate block

    // ---- stage B_hi ----
    {
        const uint4* src = (const uint4*)g_Bhi;
        uint4* dst = (uint4*)(smem + OFF_B);
        for (int i = tid; i < G3_ * KP_ * 2 / 16; i += 256) dst[i] = src[i];
    }
    // ---- convert h -> A_hi/A_lo ----
    {
        const float4* hp = (const float4*)(h + (size_t)cta * 128 * 128);
        for (int i = tid; i < 4096; i += 256) {
            int row = i >> 5, q = i & 31;
            float4 v = hp[i];
            uint2 hi2 = make_uint2(pack_bf2(v.x, v.y), pack_bf2(v.z, v.w));
            uint2 lo2 = make_uint2(pack_bf2_res(v.x, v.y), pack_bf2_res(v.z, v.w));
            *(uint2*)(smem + OFF_AH + row * 304 + q * 8) = hi2;
            *(uint2*)(smem + OFF_AL + row * 304 + q * 8) = lo2;
        }
    }
    // ---- jets cols + fp32 copies, W_jn, bhh_n ----
    if (tid < 128) {
        int row = tid;
        const float4* jp = (const float4*)(jets + (size_t)(cta * 128 + row) * FE_);
        float4 j0 = jp[0], j1 = jp[1];
        *(float4*)(smem + OFF_JET + row * 32)      = j0;
        *(float4*)(smem + OFF_JET + row * 32 + 16) = j1;
        uint4 jh = make_uint4(pack_bf2(j0.x, j0.y), pack_bf2(j0.z, j0.w),
                              pack_bf2(j1.x, j1.y), pack_bf2(j1.z, j1.w));
        uint4 jl = make_uint4(pack_bf2_res(j0.x, j0.y), pack_bf2_res(j0.z, j0.w),
                              pack_bf2_res(j1.x, j1.y), pack_bf2_res(j1.z, j1.w));
        uint4 zz = make_uint4(0, 0, 0, 0);
        *(uint4*)(smem + OFF_AH + row * 304 + 256) = jh;
        *(uint4*)(smem + OFF_AH + row * 304 + 272) = zz;
        *(uint4*)(smem + OFF_AH + row * 304 + 288) = zz;
        *(uint4*)(smem + OFF_AL + row * 304 + 256) = jl;
        *(uint4*)(smem + OFF_AL + row * 304 + 272) = zz;
        *(uint4*)(smem + OFF_AL + row * 304 + 288) = zz;
        const float4* wp = (const float4*)(Wih + (size_t)(2 * H_ + row) * KX_ + H_);
        *(float4*)(smem + OFF_WJN + row * 32)      = wp[0];
        *(float4*)(smem + OFF_WJN + row * 32 + 16) = wp[1];
        ((float*)(smem + OFF_BHHN))[row] = bhh[2 * H_ + row];
    }
    for (int g = tid; g < G3_; g += 256)
        ((float*)(smem + OFF_BIAS))[g] = g_bias[cta * G3_ + g];
    __syncthreads();

    const uint32_t sb = smem_u32(smem);
    // ldmatrix lane addresses
    const uint32_t aLane = (uint32_t)((lane & 7) + ((lane & 8) ? 8 : 0) + wm * 64) * 304
                         + ((lane & 16) ? 16 : 0);
    const uint32_t bLane = sb + OFF_B
                         + (uint32_t)((lane & 7) + ((lane & 16) ? 8 : 0) + wn * 32) * 304
                         + ((lane & 8) ? 16 : 0);

    // acc[gate][mt][nt][frag]
    float acc[3][4][4][4];
    #pragma unroll
    for (int g = 0; g < 3; g++)
        #pragma unroll
        for (int m = 0; m < 4; m++)
            #pragma unroll
            for (int n = 0; n < 4; n++) {
                acc[g][m][n][0] = 0.f; acc[g][m][n][1] = 0.f;
                acc[g][m][n][2] = 0.f; acc[g][m][n][3] = 0.f;
            }

    #pragma unroll 1
    for (int pass = 0; pass < 3; pass++) {
        if (pass == 2) {
            __syncthreads();
            const uint4* src = (const uint4*)g_Blo;
            uint4* dst = (uint4*)(smem + OFF_B);
            for (int i = tid; i < G3_ * KP_ * 2 / 16; i += 256) dst[i] = src[i];
            __syncthreads();
        }
        const uint32_t aOff = sb + ((pass == 1) ? OFF_AL : OFF_AH) + aLane;
        #pragma unroll 1
        for (int ks = 0; ks < KSTEPS; ks++) {
            // B fragments: 3 gates x 2 pairs, each x4 = 2 n-tiles
            uint32_t Bf[3][2][4];
            #pragma unroll
            for (int g = 0; g < 3; g++)
                #pragma unroll
                for (int p = 0; p < 2; p++)
                    ldm_x4(Bf[g][p], bLane + (uint32_t)(g * 128 + p * 16) * 304 + ks * 32);
            #pragma unroll
            for (int mt = 0; mt < 4; mt++) {
                uint32_t Af[4];
                ldm_x4(Af, aOff + (uint32_t)mt * 16 * 304 + ks * 32);
                #pragma unroll
                for (int g = 0; g < 3; g++) {
                    #pragma unroll
                    for (int p = 0; p < 2; p++) {
                        MMA16816(acc[g][mt][p * 2 + 0], Af[0], Af[1], Af[2], Af[3],
                                 Bf[g][p][0], Bf[g][p][1]);
                        MMA16816(acc[g][mt][p * 2 + 1], Af[0], Af[1], Af[2], Af[3],
                                 Bf[g][p][2], Bf[g][p][3]);
                    }
                }
            }
        }
    }

    // ---- GRU epilogue (warp-local: each warp owns rows wm*64.. x gate-cols wn*32..) ----
    {
        const float* biasS = (const float*)(smem + OFF_BIAS);
        const float* bhhnS = (const float*)(smem + OFF_BHHN);
        const size_t mBase = (size_t)cta * 128;
        #pragma unroll
        for (int mt = 0; mt < 4; mt++) {
            #pragma unroll
            for (int half = 0; half < 2; half++) {
                const int row = wm * 64 + mt * 16 + (lane >> 2) + half * 8;
                float4 ja = *(const float4*)(smem + OFF_JET + row * 32);
                float4 jb = *(const float4*)(smem + OFF_JET + row * 32 + 16);
                #pragma unroll
                for (int nt = 0; nt < 4; nt++) {
                    const int c = wn * 32 + nt * 8 + (lane & 3) * 2;
                    uint32_t hh = *(const uint32_t*)(smem + OFF_AH + row * 304 + c * 2);
                    uint32_t hl = *(const uint32_t*)(smem + OFF_AL + row * 304 + c * 2);
                    float o[2];
                    #pragma unroll
                    for (int e = 0; e < 2; e++) {
                        const int g = c + e;
                        const int fr = half * 2 + e;
                        float aR = acc[0][mt][nt][fr];
                        float aZ = acc[1][mt][nt][fr];
                        float aN = acc[2][mt][nt][fr];
                        float4 wa = *(const float4*)(smem + OFF_WJN + g * 32);
                        float4 wb = *(const float4*)(smem + OFF_WJN + g * 32 + 16);
                        float jd = ja.x * wa.x + ja.y * wa.y + ja.z * wa.z + ja.w * wa.w
                                 + jb.x * wb.x + jb.y * wb.y + jb.z * wb.z + jb.w * wb.w;
                        float r = 1.f / (1.f + __expf(-(aR + biasS[g])));
                        float z = 1.f / (1.f + __expf(-(aZ + biasS[128 + g])));
                        float n = tanhf(jd + biasS[256 + g] + r * (aN + bhhnS[g]));
                        float hv = (e ? bf_hi(hh) : bf_lo(hh)) + (e ? bf_hi(hl) : bf_lo(hl));
                        o[e] = (1.f - z) * n + z * hv;
                    }
                    *(float2*)(out + (mBase + row) * 128 + c) = make_float2(o[0], o[1]);
                }
            }
        }
    }
}

extern "C" void kernel_launch(void* const* d_in, const int* in_sizes, int n_in,
                              void* d_out, int out_size) {
    const float* h    = (const float*)d_in[0];
    const float* jets = (const float*)d_in[1];
    // d_in[2] = mask (unused)
    const float* Wm   = (const float*)d_in[3];
    const float* bm   = (const float*)d_in[4];
    const float* Wih  = (const float*)d_in[5];
    const float* Whh  = (const float*)d_in[6];
    const float* bih  = (const float*)d_in[7];
    const float* bhh  = (const float*)d_in[8];
    float* out = (float*)d_out;

    cudaFuncSetAttribute(k_main, cudaFuncAttributeMaxDynamicSharedMemorySize, SMEM_SZ);

    k_prep<<<(G3_ * KP_ + 255) / 256, 256>>>(Whh, Wih);
    k_rowsum<<<B_, 256>>>(h);
    k_bias<<<B_, H_>>>(Wm, bm, Wih, bih, bhh);
    k_main<<<B_, 256, SMEM_SZ>>>(h, jets, Wih, bhh, out);
}

// round 6
// speedup vs baseline: 1.6003x; 1.6003x over previous
#include <cuda_runtime.h>
#include <cuda_bf16.h>
#include <cstdint>

#define B_  1024
#define N_  128
#define H_  128
#define FE_ 8
#define G3_ 384
#define KX_ 136
#define KSTEPS 9         // K = 144 (128 h + 8 jets + 8 zero)

// ---------------- device scratch ----------------
__device__ __align__(16) float g_hs[B_ * H_];
__device__ __align__(16) float g_bias[B_ * G3_];
// B in MMA-fragment order: [ks][hi/lo][pair p=nt/2 (24)][lane (32)] uint4 = (t0.b0,t0.b1,t1.b0,t1.b1)
__device__ __align__(16) uint4 g_Bp[KSTEPS * 1536];

__device__ __forceinline__ uint32_t pack_bf2(float a, float b) {
    __nv_bfloat16 ah = __float2bfloat16(a), bh = __float2bfloat16(b);
    return (uint32_t)__bfloat16_as_ushort(ah) | ((uint32_t)__bfloat16_as_ushort(bh) << 16);
}
__device__ __forceinline__ uint32_t pack_bf2_res(float a, float b) {
    __nv_bfloat16 ah = __float2bfloat16(a), bh = __float2bfloat16(b);
    float ar = a - __bfloat162float(ah), br = b - __bfloat162float(bh);
    return (uint32_t)__bfloat16_as_ushort(__float2bfloat16(ar))
         | ((uint32_t)__bfloat16_as_ushort(__float2bfloat16(br)) << 16);
}
__device__ __forceinline__ float bf_lo(uint32_t u) {
    return __bfloat162float(__ushort_as_bfloat16((unsigned short)(u & 0xffff)));
}
__device__ __forceinline__ float bf_hi(uint32_t u) {
    return __bfloat162float(__ushort_as_bfloat16((unsigned short)(u >> 16)));
}

#define MMA16816(ac, a0, a1, a2, a3, b0, b1)                                   \
    asm volatile("mma.sync.aligned.m16n8k16.row.col.f32.bf16.bf16.f32 "        \
                 "{%0,%1,%2,%3}, {%4,%5,%6,%7}, {%8,%9}, {%0,%1,%2,%3};"       \
                 : "+f"((ac)[0]), "+f"((ac)[1]), "+f"((ac)[2]), "+f"((ac)[3])  \
                 : "r"(a0), "r"(a1), "r"(a2), "r"(a3), "r"(b0), "r"(b1))

// ---------------- prep: permute weights into fragment order (hi/lo split) ----------------
__global__ void k_prep(const float* __restrict__ Whh, const float* __restrict__ Wih) {
    int i = blockIdx.x * 256 + threadIdx.x;
    if (i >= KSTEPS * 48 * 32) return;
    int ks = i / 1536, rem = i % 1536;
    int nt = rem >> 5, lane = rem & 31;
    int n = nt * 8 + (lane >> 2);
    int k0 = ks * 16 + (lane & 3) * 2;
    float w[4];
    #pragma unroll
    for (int q = 0; q < 4; q++) {
        int k = k0 + (q >> 1) * 8 + (q & 1);
        float v = 0.f;
        if (k < H_) v = Whh[n * H_ + k];
        else if (k < H_ + FE_ && n < 2 * H_) v = Wih[(size_t)n * KX_ + k];  // jets cols for r,z
        w[q] = v;
    }
    uint2 hiv = make_uint2(pack_bf2(w[0], w[1]), pack_bf2(w[2], w[3]));
    uint2 lov = make_uint2(pack_bf2_res(w[0], w[1]), pack_bf2_res(w[2], w[3]));
    uint2* bp = (uint2*)g_Bp;
    int p = nt >> 1, half = nt & 1;
    bp[(ks * 1536 + 0   + p * 32 + lane) * 2 + half] = hiv;
    bp[(ks * 1536 + 768 + p * 32 + lane) * 2 + half] = lov;
}

// ---------------- rowsum ----------------
__global__ void k_rowsum(const float* __restrict__ h) {
    __shared__ float4 red[256];
    int b = blockIdx.x, tid = threadIdx.x;
    int k4 = tid & 31, n0 = tid >> 5;
    const float4* p = (const float4*)(h + (size_t)b * N_ * H_) + k4;
    float4 s = make_float4(0.f, 0.f, 0.f, 0.f);
    #pragma unroll
    for (int j = 0; j < 16; j++) {
        float4 v = p[(size_t)(n0 + 8 * j) * 32];
        s.x += v.x; s.y += v.y; s.z += v.z; s.w += v.w;
    }
    red[tid] = s;
    __syncthreads();
    #pragma unroll
    for (int off = 128; off >= 32; off >>= 1) {
        if (tid < off) {
            float4 a = red[tid], c = red[tid + off];
            a.x += c.x; a.y += c.y; a.z += c.z; a.w += c.w;
            red[tid] = a;
        }
        __syncthreads();
    }
    if (tid < 32) ((float4*)g_hs)[b * 32 + tid] = red[tid];
}

// ---------------- bias ----------------
__global__ void k_bias(const float* __restrict__ Wm, const float* __restrict__ bm,
                       const float* __restrict__ Wih, const float* __restrict__ bih,
                       const float* __restrict__ bhh) {
    __shared__ float hsS[H_];
    __shared__ float msgS[H_];
    int b = blockIdx.x;
    int k = threadIdx.x;
    hsS[k] = g_hs[b * H_ + k];
    __syncthreads();
    const float4* wr = (const float4*)(Wm + (size_t)k * H_);
    float d = 0.f;
    #pragma unroll
    for (int j = 0; j < H_ / 4; j++) {
        float4 w = wr[j];
        d += hsS[4 * j + 0] * w.x + hsS[4 * j + 1] * w.y
           + hsS[4 * j + 2] * w.z + hsS[4 * j + 3] * w.w;
    }
    msgS[k] = tanhf(d + (float)N_ * bm[k]);
    __syncthreads();
    #pragma unroll
    for (int q = 0; q < 3; q++) {
        int g = q * H_ + k;
        const float4* wi = (const float4*)(Wih + (size_t)g * KX_);
        float d2 = 0.f;
        #pragma unroll
        for (int j = 0; j < H_ / 4; j++) {
            float4 w = wi[j];
            d2 += msgS[4 * j + 0] * w.x + msgS[4 * j + 1] * w.y
                + msgS[4 * j + 2] * w.z + msgS[4 * j + 3] * w.w;
        }
        float bias = d2 + bih[g];
        if (g < 2 * H_) bias += bhh[g];
        g_bias[b * G3_ + g] = bias;
    }
}

// ---------------- smem layout (bytes) ----------------
#define OFF_AH   0            // 19456  A_hi [64][152] bf16, 304B row stride
#define OFF_AL   19456        // 19456
#define OFF_BB   38912        // 49152  B double buffer: 2 x (hi 12288 + lo 12288)
#define OFF_JET  88064        //  2048  jets fp32 [64][8]
#define OFF_WJN  90112        //  4096  W_ih n-gate jets cols fp32 [128][8]
#define OFF_BIAS 94208        //  1536
#define OFF_BHHN 95744        //   512
#define SMEM_SZ  96256

// ---------------- main: 512 threads, 64 rows x 384 cols per CTA ----------------
__global__ void __launch_bounds__(512, 1) k_main(
    const float* __restrict__ h, const float* __restrict__ jets,
    const float* __restrict__ Wih, const float* __restrict__ bhh,
    float* __restrict__ out)
{
    extern __shared__ char smem[];
    const int tid  = threadIdx.x;
    const int wid  = tid >> 5;
    const int lane = tid & 31;
    const int cta  = blockIdx.x;        // 64 rows each, 2 CTAs per batch
    const int wn   = wid & 7;           // 8 N-positions: 16 cols per gate each
    const int wm   = wid >> 3;          // 2 M-positions: 32 rows each
    const int batch = cta >> 1;

    // ---- stage B chunk 0 ----
    {
        uint4* dst = (uint4*)(smem + OFF_BB);
        dst[tid]        = g_Bp[tid];
        dst[tid + 512]  = g_Bp[tid + 512];
        dst[tid + 1024] = g_Bp[tid + 1024];
    }
    // ---- convert h -> A_hi / A_lo ----
    {
        const float4* hp = (const float4*)(h + (size_t)cta * 64 * 128);
        #pragma unroll
        for (int i = tid; i < 2048; i += 512) {
            int row = i >> 5, q = i & 31;
            float4 v = hp[i];
            uint2 hi2 = make_uint2(pack_bf2(v.x, v.y), pack_bf2(v.z, v.w));
            uint2 lo2 = make_uint2(pack_bf2_res(v.x, v.y), pack_bf2_res(v.z, v.w));
            *(uint2*)(smem + OFF_AH + row * 304 + q * 8) = hi2;
            *(uint2*)(smem + OFF_AL + row * 304 + q * 8) = lo2;
        }
    }
    // ---- jets cols (A K 128..151) + fp32 jets ----
    if (tid < 64) {
        int row = tid;
        const float4* jp = (const float4*)(jets + (size_t)(cta * 64 + row) * FE_);
        float4 j0 = jp[0], j1 = jp[1];
        *(float4*)(smem + OFF_JET + row * 32)      = j0;
        *(float4*)(smem + OFF_JET + row * 32 + 16) = j1;
        uint4 jh = make_uint4(pack_bf2(j0.x, j0.y), pack_bf2(j0.z, j0.w),
                              pack_bf2(j1.x, j1.y), pack_bf2(j1.z, j1.w));
        uint4 jl = make_uint4(pack_bf2_res(j0.x, j0.y), pack_bf2_res(j0.z, j0.w),
                              pack_bf2_res(j1.x, j1.y), pack_bf2_res(j1.z, j1.w));
        uint4 zz = make_uint4(0, 0, 0, 0);
        *(uint4*)(smem + OFF_AH + row * 304 + 256) = jh;
        *(uint4*)(smem + OFF_AH + row * 304 + 272) = zz;
        *(uint4*)(smem + OFF_AH + row * 304 + 288) = zz;
        *(uint4*)(smem + OFF_AL + row * 304 + 256) = jl;
        *(uint4*)(smem + OFF_AL + row * 304 + 272) = zz;
        *(uint4*)(smem + OFF_AL + row * 304 + 288) = zz;
    }
    // ---- W_ih n-gate jets cols, bias, bhh_n ----
    if (tid < 128) {
        const float4* wp = (const float4*)(Wih + (size_t)(2 * H_ + tid) * KX_ + H_);
        *(float4*)(smem + OFF_WJN + tid * 32)      = wp[0];
        *(float4*)(smem + OFF_WJN + tid * 32 + 16) = wp[1];
        ((float*)(smem + OFF_BHHN))[tid] = bhh[2 * H_ + tid];
    }
    if (tid < G3_)
        ((float*)(smem + OFF_BIAS))[tid] = g_bias[batch * G3_ + tid];
    __syncthreads();

    // acc[gate][mt][j][frag]
    float acc[3][2][2][4];
    #pragma unroll
    for (int g = 0; g < 3; g++)
        #pragma unroll
        for (int m = 0; m < 2; m++)
            #pragma unroll
            for (int j = 0; j < 2; j++) {
                acc[g][m][j][0] = 0.f; acc[g][m][j][1] = 0.f;
                acc[g][m][j][2] = 0.f; acc[g][m][j][3] = 0.f;
            }

    const uint32_t aRowOff = (uint32_t)(wm * 32 + (lane >> 2)) * 304 + (lane & 3) * 4;

    #pragma unroll 1
    for (int ks = 0; ks < KSTEPS; ks++) {
        uint4 s0, s1, s2;
        if (ks < KSTEPS - 1) {
            const uint4* src = g_Bp + (ks + 1) * 1536;
            s0 = src[tid]; s1 = src[tid + 512]; s2 = src[tid + 1024];
        }
        const char* bb = smem + OFF_BB + (ks & 1) * 24576;

        // A fragments (hi + lo, 2 m-tiles)
        uint32_t ah[2][4], al[2][4];
        #pragma unroll
        for (int mt = 0; mt < 2; mt++) {
            const char* pa = smem + OFF_AH + aRowOff + mt * 16 * 304 + ks * 32;
            const char* pl = smem + OFF_AL + aRowOff + mt * 16 * 304 + ks * 32;
            ah[mt][0] = *(const uint32_t*)(pa);
            ah[mt][1] = *(const uint32_t*)(pa + 2432);
            ah[mt][2] = *(const uint32_t*)(pa + 16);
            ah[mt][3] = *(const uint32_t*)(pa + 2448);
            al[mt][0] = *(const uint32_t*)(pl);
            al[mt][1] = *(const uint32_t*)(pl + 2432);
            al[mt][2] = *(const uint32_t*)(pl + 16);
            al[mt][3] = *(const uint32_t*)(pl + 2448);
        }
        #pragma unroll
        for (int g = 0; g < 3; g++) {
            const char* pb = bb + ((g * 8 + wn) * 32 + lane) * 16;
            uint4 bh = *(const uint4*)(pb);
            uint4 bl = *(const uint4*)(pb + 12288);
            #pragma unroll
            for (int mt = 0; mt < 2; mt++) {
                MMA16816(acc[g][mt][0], ah[mt][0], ah[mt][1], ah[mt][2], ah[mt][3], bh.x, bh.y);
                MMA16816(acc[g][mt][1], ah[mt][0], ah[mt][1], ah[mt][2], ah[mt][3], bh.z, bh.w);
                MMA16816(acc[g][mt][0], al[mt][0], al[mt][1], al[mt][2], al[mt][3], bh.x, bh.y);
                MMA16816(acc[g][mt][1], al[mt][0], al[mt][1], al[mt][2], al[mt][3], bh.z, bh.w);
                MMA16816(acc[g][mt][0], ah[mt][0], ah[mt][1], ah[mt][2], ah[mt][3], bl.x, bl.y);
                MMA16816(acc[g][mt][1], ah[mt][0], ah[mt][1], ah[mt][2], ah[mt][3], bl.z, bl.w);
            }
        }
        if (ks < KSTEPS - 1) {
            uint4* dst = (uint4*)(smem + OFF_BB + ((ks + 1) & 1) * 24576);
            dst[tid] = s0; dst[tid + 512] = s1; dst[tid + 1024] = s2;
        }
        __syncthreads();
    }

    // ---- GRU epilogue (warp-local) ----
    {
        const float* biasS = (const float*)(smem + OFF_BIAS);
        const float* bhhnS = (const float*)(smem + OFF_BHHN);
        const size_t mBase = (size_t)cta * 64;
        #pragma unroll
        for (int mt = 0; mt < 2; mt++) {
            #pragma unroll
            for (int half = 0; half < 2; half++) {
                const int row = wm * 32 + mt * 16 + (lane >> 2) + half * 8;
                float4 ja = *(const float4*)(smem + OFF_JET + row * 32);
                float4 jb = *(const float4*)(smem + OFF_JET + row * 32 + 16);
                #pragma unroll
                for (int j = 0; j < 2; j++) {
                    const int c = wn * 16 + j * 8 + (lane & 3) * 2;
                    uint32_t hh = *(const uint32_t*)(smem + OFF_AH + row * 304 + c * 2);
                    uint32_t hl = *(const uint32_t*)(smem + OFF_AL + row * 304 + c * 2);
                    float o[2];
                    #pragma unroll
                    for (int e = 0; e < 2; e++) {
                        const int g = c + e;
                        const int fr = half * 2 + e;
                        float aR = acc[0][mt][j][fr];
                        float aZ = acc[1][mt][j][fr];
                        float aN = acc[2][mt][j][fr];
                        float4 wa = *(const float4*)(smem + OFF_WJN + g * 32);
                        float4 wb = *(const float4*)(smem + OFF_WJN + g * 32 + 16);
                        float jd = ja.x * wa.x + ja.y * wa.y + ja.z * wa.z + ja.w * wa.w
                                 + jb.x * wb.x + jb.y * wb.y + jb.z * wb.z + jb.w * wb.w;
                        float r = 1.f / (1.f + __expf(-(aR + biasS[g])));
                        float z = 1.f / (1.f + __expf(-(aZ + biasS[128 + g])));
                        float n = tanhf(jd + biasS[256 + g] + r * (aN + bhhnS[g]));
                        float hv = (e ? bf_hi(hh) : bf_lo(hh)) + (e ? bf_hi(hl) : bf_lo(hl));
                        o[e] = (1.f - z) * n + z * hv;
                    }
                    *(float2*)(out + (mBase + row) * 128 + c) = make_float2(o[0], o[1]);
                }
            }
        }
    }
}

extern "C" void kernel_launch(void* const* d_in, const int* in_sizes, int n_in,
                              void* d_out, int out_size) {
    const float* h    = (const float*)d_in[0];
    const float* jets = (const float*)d_in[1];
    // d_in[2] = mask (unused)
    const float* Wm   = (const float*)d_in[3];
    const float* bm   = (const float*)d_in[4];
    const float* Wih  = (const float*)d_in[5];
    const float* Whh  = (const float*)d_in[6];
    const float* bih  = (const float*)d_in[7];
    const float* bhh  = (const float*)d_in[8];
    float* out = (float*)d_out;

    cudaFuncSetAttribute(k_main, cudaFuncAttributeMaxDynamicSharedMemorySize, SMEM_SZ);

    k_prep<<<(KSTEPS * 48 * 32 + 255) / 256, 256>>>(Whh, Wih);
    k_rowsum<<<B_, 256>>>(h);
    k_bias<<<B_, H_>>>(Wm, bm, Wih, bih, bhh);
    k_main<<<2 * B_, 512, SMEM_SZ>>>(h, jets, Wih, bhh, out);
}

// round 7
// speedup vs baseline: 1.8585x; 1.1614x over previous
#include <cuda_runtime.h>
#include <cuda_bf16.h>
#include <cstdint>

#define B_  1024
#define N_  128
#define H_  128
#define FE_ 8
#define G3_ 384
#define KX_ 136
#define KSTEPS 9         // K = 144 (128 h + 8 jets + 8 zero)

// ---------------- device scratch ----------------
__device__ __align__(16) float g_hs[B_ * H_];
__device__ __align__(16) float g_bias[B_ * G3_];
// B in MMA-fragment order: [ks][hi/lo][pair p=nt/2 (24)][lane (32)] uint4 = (t0.b0,t0.b1,t1.b0,t1.b1)
__device__ __align__(16) uint4 g_Bp[KSTEPS * 1536];

__device__ __forceinline__ uint32_t pack_bf2(float a, float b) {
    __nv_bfloat16 ah = __float2bfloat16(a), bh = __float2bfloat16(b);
    return (uint32_t)__bfloat16_as_ushort(ah) | ((uint32_t)__bfloat16_as_ushort(bh) << 16);
}
__device__ __forceinline__ uint32_t pack_bf2_res(float a, float b) {
    __nv_bfloat16 ah = __float2bfloat16(a), bh = __float2bfloat16(b);
    float ar = a - __bfloat162float(ah), br = b - __bfloat162float(bh);
    return (uint32_t)__bfloat16_as_ushort(__float2bfloat16(ar))
         | ((uint32_t)__bfloat16_as_ushort(__float2bfloat16(br)) << 16);
}
__device__ __forceinline__ float bf_lo(uint32_t u) {
    return __bfloat162float(__ushort_as_bfloat16((unsigned short)(u & 0xffff)));
}
__device__ __forceinline__ float bf_hi(uint32_t u) {
    return __bfloat162float(__ushort_as_bfloat16((unsigned short)(u >> 16)));
}

#define MMA16816(ac, a0, a1, a2, a3, b0, b1)                                   \
    asm volatile("mma.sync.aligned.m16n8k16.row.col.f32.bf16.bf16.f32 "        \
                 "{%0,%1,%2,%3}, {%4,%5,%6,%7}, {%8,%9}, {%0,%1,%2,%3};"       \
                 : "+f"((ac)[0]), "+f"((ac)[1]), "+f"((ac)[2]), "+f"((ac)[3])  \
                 : "r"(a0), "r"(a1), "r"(a2), "r"(a3), "r"(b0), "r"(b1))

// ---------------- prep: permute weights into fragment order (hi/lo split) ----------------
__global__ void k_prep(const float* __restrict__ Whh, const float* __restrict__ Wih) {
    int i = blockIdx.x * 256 + threadIdx.x;
    if (i >= KSTEPS * 48 * 32) return;
    int ks = i / 1536, rem = i % 1536;
    int nt = rem >> 5, lane = rem & 31;
    int n = nt * 8 + (lane >> 2);
    int k0 = ks * 16 + (lane & 3) * 2;
    float w[4];
    #pragma unroll
    for (int q = 0; q < 4; q++) {
        int k = k0 + (q >> 1) * 8 + (q & 1);
        float v = 0.f;
        if (k < H_) v = Whh[n * H_ + k];
        else if (k < H_ + FE_ && n < 2 * H_) v = Wih[(size_t)n * KX_ + k];  // jets cols for r,z
        w[q] = v;
    }
    uint2 hiv = make_uint2(pack_bf2(w[0], w[1]), pack_bf2(w[2], w[3]));
    uint2 lov = make_uint2(pack_bf2_res(w[0], w[1]), pack_bf2_res(w[2], w[3]));
    uint2* bp = (uint2*)g_Bp;
    int p = nt >> 1, half = nt & 1;
    bp[(ks * 1536 + 0   + p * 32 + lane) * 2 + half] = hiv;
    bp[(ks * 1536 + 768 + p * 32 + lane) * 2 + half] = lov;
}

// ---------------- rowsum ----------------
__global__ void k_rowsum(const float* __restrict__ h) {
    __shared__ float4 red[256];
    int b = blockIdx.x, tid = threadIdx.x;
    int k4 = tid & 31, n0 = tid >> 5;
    const float4* p = (const float4*)(h + (size_t)b * N_ * H_) + k4;
    float4 s = make_float4(0.f, 0.f, 0.f, 0.f);
    #pragma unroll
    for (int j = 0; j < 16; j++) {
        float4 v = p[(size_t)(n0 + 8 * j) * 32];
        s.x += v.x; s.y += v.y; s.z += v.z; s.w += v.w;
    }
    red[tid] = s;
    __syncthreads();
    #pragma unroll
    for (int off = 128; off >= 32; off >>= 1) {
        if (tid < off) {
            float4 a = red[tid], c = red[tid + off];
            a.x += c.x; a.y += c.y; a.z += c.z; a.w += c.w;
            red[tid] = a;
        }
        __syncthreads();
    }
    if (tid < 32) ((float4*)g_hs)[b * 32 + tid] = red[tid];
}

// ---------------- bias ----------------
__global__ void k_bias(const float* __restrict__ Wm, const float* __restrict__ bm,
                       const float* __restrict__ Wih, const float* __restrict__ bih,
                       const float* __restrict__ bhh) {
    __shared__ float hsS[H_];
    __shared__ float msgS[H_];
    int b = blockIdx.x;
    int k = threadIdx.x;
    hsS[k] = g_hs[b * H_ + k];
    __syncthreads();
    const float4* wr = (const float4*)(Wm + (size_t)k * H_);
    float d = 0.f;
    #pragma unroll
    for (int j = 0; j < H_ / 4; j++) {
        float4 w = wr[j];
        d += hsS[4 * j + 0] * w.x + hsS[4 * j + 1] * w.y
           + hsS[4 * j + 2] * w.z + hsS[4 * j + 3] * w.w;
    }
    msgS[k] = tanhf(d + (float)N_ * bm[k]);
    __syncthreads();
    #pragma unroll
    for (int q = 0; q < 3; q++) {
        int g = q * H_ + k;
        const float4* wi = (const float4*)(Wih + (size_t)g * KX_);
        float d2 = 0.f;
        #pragma unroll
        for (int j = 0; j < H_ / 4; j++) {
            float4 w = wi[j];
            d2 += msgS[4 * j + 0] * w.x + msgS[4 * j + 1] * w.y
                + msgS[4 * j + 2] * w.z + msgS[4 * j + 3] * w.w;
        }
        float bias = d2 + bih[g];
        if (g < 2 * H_) bias += bhh[g];
        g_bias[b * G3_ + g] = bias;
    }
}

// ---------------- smem layout (bytes) ----------------
#define OFF_AH   0            // 19456  A_hi [64][152] bf16, 304B row stride
#define OFF_AL   19456        // 19456
#define OFF_JET  38912        //  2048  jets fp32 [64][8]
#define OFF_WJN  40960        //  4096  W_ih n-gate jets cols fp32 [128][8]
#define OFF_BIAS 45056        //  1536
#define OFF_BHHN 46592        //   512
#define SMEM_SZ  47104

// ---------------- main: 512 threads, 64 rows x 384 cols per CTA ----------------
__global__ void __launch_bounds__(512, 1) k_main(
    const float* __restrict__ h, const float* __restrict__ jets,
    const float* __restrict__ Wih, const float* __restrict__ bhh,
    float* __restrict__ out)
{
    extern __shared__ char smem[];
    const int tid  = threadIdx.x;
    const int wid  = tid >> 5;
    const int lane = tid & 31;
    const int cta  = blockIdx.x;        // 64 rows each, 2 CTAs per batch
    const int wn   = wid & 7;           // 8 N-positions: 16 cols per gate each
    const int wm   = wid >> 3;          // 2 M-positions: 32 rows each
    const int batch = cta >> 1;

    // ---- convert h -> A_hi / A_lo ----
    {
        const float4* hp = (const float4*)(h + (size_t)cta * 64 * 128);
        #pragma unroll
        for (int i = tid; i < 2048; i += 512) {
            int row = i >> 5, q = i & 31;
            float4 v = hp[i];
            uint2 hi2 = make_uint2(pack_bf2(v.x, v.y), pack_bf2(v.z, v.w));
            uint2 lo2 = make_uint2(pack_bf2_res(v.x, v.y), pack_bf2_res(v.z, v.w));
            *(uint2*)(smem + OFF_AH + row * 304 + q * 8) = hi2;
            *(uint2*)(smem + OFF_AL + row * 304 + q * 8) = lo2;
        }
    }
    // ---- jets cols (A K 128..151) + fp32 jets ----
    if (tid < 64) {
        int row = tid;
        const float4* jp = (const float4*)(jets + (size_t)(cta * 64 + row) * FE_);
        float4 j0 = jp[0], j1 = jp[1];
        *(float4*)(smem + OFF_JET + row * 32)      = j0;
        *(float4*)(smem + OFF_JET + row * 32 + 16) = j1;
        uint4 jh = make_uint4(pack_bf2(j0.x, j0.y), pack_bf2(j0.z, j0.w),
                              pack_bf2(j1.x, j1.y), pack_bf2(j1.z, j1.w));
        uint4 jl = make_uint4(pack_bf2_res(j0.x, j0.y), pack_bf2_res(j0.z, j0.w),
                              pack_bf2_res(j1.x, j1.y), pack_bf2_res(j1.z, j1.w));
        uint4 zz = make_uint4(0, 0, 0, 0);
        *(uint4*)(smem + OFF_AH + row * 304 + 256) = jh;
        *(uint4*)(smem + OFF_AH + row * 304 + 272) = zz;
        *(uint4*)(smem + OFF_AH + row * 304 + 288) = zz;
        *(uint4*)(smem + OFF_AL + row * 304 + 256) = jl;
        *(uint4*)(smem + OFF_AL + row * 304 + 272) = zz;
        *(uint4*)(smem + OFF_AL + row * 304 + 288) = zz;
    }
    // ---- W_ih n-gate jets cols, bias, bhh_n ----
    if (tid < 128) {
        const float4* wp = (const float4*)(Wih + (size_t)(2 * H_ + tid) * KX_ + H_);
        *(float4*)(smem + OFF_WJN + tid * 32)      = wp[0];
        *(float4*)(smem + OFF_WJN + tid * 32 + 16) = wp[1];
        ((float*)(smem + OFF_BHHN))[tid] = bhh[2 * H_ + tid];
    }
    if (tid < G3_)
        ((float*)(smem + OFF_BIAS))[tid] = g_bias[batch * G3_ + tid];
    __syncthreads();   // the ONLY barrier: A/bias visible to all warps

    // acc[gate][mt][j][frag]
    float acc[3][2][2][4];
    #pragma unroll
    for (int g = 0; g < 3; g++)
        #pragma unroll
        for (int m = 0; m < 2; m++)
            #pragma unroll
            for (int j = 0; j < 2; j++) {
                acc[g][m][j][0] = 0.f; acc[g][m][j][1] = 0.f;
                acc[g][m][j][2] = 0.f; acc[g][m][j][3] = 0.f;
            }

    const uint32_t aRowOff = (uint32_t)(wm * 32 + (lane >> 2)) * 304 + (lane & 3) * 4;
    const uint4* bBase = g_Bp + wn * 32 + lane;

    #pragma unroll
    for (int ks = 0; ks < KSTEPS; ks++) {
        // A fragments (hi + lo, 2 m-tiles) from smem
        uint32_t ah[2][4], al[2][4];
        #pragma unroll
        for (int mt = 0; mt < 2; mt++) {
            const char* pa = smem + OFF_AH + aRowOff + mt * 16 * 304 + ks * 32;
            const char* pl = smem + OFF_AL + aRowOff + mt * 16 * 304 + ks * 32;
            ah[mt][0] = *(const uint32_t*)(pa);
            ah[mt][1] = *(const uint32_t*)(pa + 2432);
            ah[mt][2] = *(const uint32_t*)(pa + 16);
            ah[mt][3] = *(const uint32_t*)(pa + 2448);
            al[mt][0] = *(const uint32_t*)(pl);
            al[mt][1] = *(const uint32_t*)(pl + 2432);
            al[mt][2] = *(const uint32_t*)(pl + 16);
            al[mt][3] = *(const uint32_t*)(pl + 2448);
        }
        // B fragments direct from global (L1/L2 resident, shared by all CTAs)
        const uint4* bp = bBase + ks * 1536;
        #pragma unroll
        for (int g = 0; g < 3; g++) {
            if (ks == KSTEPS - 1 && g == 2) continue;   // B_n rows 128..143 are zero
            uint4 bh = bp[g * 256];
            uint4 bl = bp[g * 256 + 768];
            #pragma unroll
            for (int mt = 0; mt < 2; mt++) {
                MMA16816(acc[g][mt][0], ah[mt][0], ah[mt][1], ah[mt][2], ah[mt][3], bh.x, bh.y);
                MMA16816(acc[g][mt][1], ah[mt][0], ah[mt][1], ah[mt][2], ah[mt][3], bh.z, bh.w);
                MMA16816(acc[g][mt][0], al[mt][0], al[mt][1], al[mt][2], al[mt][3], bh.x, bh.y);
                MMA16816(acc[g][mt][1], al[mt][0], al[mt][1], al[mt][2], al[mt][3], bh.z, bh.w);
                MMA16816(acc[g][mt][0], ah[mt][0], ah[mt][1], ah[mt][2], ah[mt][3], bl.x, bl.y);
                MMA16816(acc[g][mt][1], ah[mt][0], ah[mt][1], ah[mt][2], ah[mt][3], bl.z, bl.w);
            }
        }
    }

    // ---- GRU epilogue (warp-local) ----
    {
        const float* biasS = (const float*)(smem + OFF_BIAS);
        const float* bhhnS = (const float*)(smem + OFF_BHHN);
        const size_t mBase = (size_t)cta * 64;
        #pragma unroll
        for (int mt = 0; mt < 2; mt++) {
            #pragma unroll
            for (int half = 0; half < 2; half++) {
                const int row = wm * 32 + mt * 16 + (lane >> 2) + half * 8;
                float4 ja = *(const float4*)(smem + OFF_JET + row * 32);
                float4 jb = *(const float4*)(smem + OFF_JET + row * 32 + 16);
                #pragma unroll
                for (int j = 0; j < 2; j++) {
                    const int c = wn * 16 + j * 8 + (lane & 3) * 2;
                    uint32_t hh = *(const uint32_t*)(smem + OFF_AH + row * 304 + c * 2);
                    uint32_t hl = *(const uint32_t*)(smem + OFF_AL + row * 304 + c * 2);
                    float o[2];
                    #pragma unroll
                    for (int e = 0; e < 2; e++) {
                        const int g = c + e;
                        const int fr = half * 2 + e;
                        float aR = acc[0][mt][j][fr];
                        float aZ = acc[1][mt][j][fr];
                        float aN = acc[2][mt][j][fr];
                        float4 wa = *(const float4*)(smem + OFF_WJN + g * 32);
                        float4 wb = *(const float4*)(smem + OFF_WJN + g * 32 + 16);
                        float jd = ja.x * wa.x + ja.y * wa.y + ja.z * wa.z + ja.w * wa.w
                                 + jb.x * wb.x + jb.y * wb.y + jb.z * wb.z + jb.w * wb.w;
                        float r = 1.f / (1.f + __expf(-(aR + biasS[g])));
                        float z = 1.f / (1.f + __expf(-(aZ + biasS[128 + g])));
                        float n = tanhf(jd + biasS[256 + g] + r * (aN + bhhnS[g]));
                        float hv = (e ? bf_hi(hh) : bf_lo(hh)) + (e ? bf_hi(hl) : bf_lo(hl));
                        o[e] = (1.f - z) * n + z * hv;
                    }
                    *(float2*)(out + (mBase + row) * 128 + c) = make_float2(o[0], o[1]);
                }
            }
        }
    }
}

extern "C" void kernel_launch(void* const* d_in, const int* in_sizes, int n_in,
                              void* d_out, int out_size) {
    const float* h    = (const float*)d_in[0];
    const float* jets = (const float*)d_in[1];
    // d_in[2] = mask (unused)
    const float* Wm   = (const float*)d_in[3];
    const float* bm   = (const float*)d_in[4];
    const float* Wih  = (const float*)d_in[5];
    const float* Whh  = (const float*)d_in[6];
    const float* bih  = (const float*)d_in[7];
    const float* bhh  = (const float*)d_in[8];
    float* out = (float*)d_out;

    cudaFuncSetAttribute(k_main, cudaFuncAttributeMaxDynamicSharedMemorySize, SMEM_SZ);

    k_prep<<<(KSTEPS * 48 * 32 + 255) / 256, 256>>>(Whh, Wih);
    k_rowsum<<<B_, 256>>>(h);
    k_bias<<<B_, H_>>>(Wm, bm, Wih, bih, bhh);
    k_main<<<2 * B_, 512, SMEM_SZ>>>(h, jets, Wih, bhh, out);
}

// round 8
// speedup vs baseline: 2.3685x; 1.2745x over previous
#include <cuda_runtime.h>
#include <cuda_bf16.h>
#include <cstdint>

#define B_  1024
#define N_  128
#define H_  128
#define FE_ 8
#define G3_ 384
#define KX_ 136
#define KSTEPS 9         // K = 144 (128 h + 8 jets + 8 zero)

// ---------------- device scratch ----------------
__device__ __align__(16) float g_bias[B_ * G3_];
// B in MMA-fragment order: [ks][hi/lo][pair p=nt/2 (24)][lane (32)] uint4
__device__ __align__(16) uint4 g_Bp[KSTEPS * 1536];

__device__ __forceinline__ uint32_t pack_bf2(float a, float b) {
    __nv_bfloat16 ah = __float2bfloat16(a), bh = __float2bfloat16(b);
    return (uint32_t)__bfloat16_as_ushort(ah) | ((uint32_t)__bfloat16_as_ushort(bh) << 16);
}
__device__ __forceinline__ uint32_t pack_bf2_res(float a, float b) {
    __nv_bfloat16 ah = __float2bfloat16(a), bh = __float2bfloat16(b);
    float ar = a - __bfloat162float(ah), br = b - __bfloat162float(bh);
    return (uint32_t)__bfloat16_as_ushort(__float2bfloat16(ar))
         | ((uint32_t)__bfloat16_as_ushort(__float2bfloat16(br)) << 16);
}
__device__ __forceinline__ float bf_lo(uint32_t u) {
    return __bfloat162float(__ushort_as_bfloat16((unsigned short)(u & 0xffff)));
}
__device__ __forceinline__ float bf_hi(uint32_t u) {
    return __bfloat162float(__ushort_as_bfloat16((unsigned short)(u >> 16)));
}
__device__ __forceinline__ float tanh_ap(float x) {
    float y;
    asm("tanh.approx.f32 %0, %1;" : "=f"(y) : "f"(x));
    return y;
}

#define MMA16816(ac, a0, a1, a2, a3, b0, b1)                                   \
    asm volatile("mma.sync.aligned.m16n8k16.row.col.f32.bf16.bf16.f32 "        \
                 "{%0,%1,%2,%3}, {%4,%5,%6,%7}, {%8,%9}, {%0,%1,%2,%3};"       \
                 : "+f"((ac)[0]), "+f"((ac)[1]), "+f"((ac)[2]), "+f"((ac)[3])  \
                 : "r"(a0), "r"(a1), "r"(a2), "r"(a3), "r"(b0), "r"(b1))

// ---------------- fused pre-kernel ----------------
// blocks [0, B_): per-batch rowsum -> message -> gate bias
// blocks [B_, B_+54): weight permute into fragment order (hi/lo split)
__global__ void __launch_bounds__(256) k_pre(
    const float* __restrict__ h,
    const float* __restrict__ Whh, const float* __restrict__ Wih,
    const float* __restrict__ Wm, const float* __restrict__ bm,
    const float* __restrict__ bih, const float* __restrict__ bhh)
{
    const int bid = blockIdx.x;
    const int tid = threadIdx.x;

    if (bid >= B_) {
        // ---- weight permute ----
        int i = (bid - B_) * 256 + tid;           // < 13824 = KSTEPS*1536
        int ks = i / 1536, rem = i % 1536;
        int nt = rem >> 5, lane = rem & 31;
        int n = nt * 8 + (lane >> 2);
        int k0 = ks * 16 + (lane & 3) * 2;
        float w[4];
        #pragma unroll
        for (int q = 0; q < 4; q++) {
            int k = k0 + (q >> 1) * 8 + (q & 1);
            float v = 0.f;
            if (k < H_) v = Whh[n * H_ + k];
            else if (k < H_ + FE_ && n < 2 * H_) v = Wih[(size_t)n * KX_ + k];
            w[q] = v;
        }
        uint2 hiv = make_uint2(pack_bf2(w[0], w[1]), pack_bf2(w[2], w[3]));
        uint2 lov = make_uint2(pack_bf2_res(w[0], w[1]), pack_bf2_res(w[2], w[3]));
        uint2* bp = (uint2*)g_Bp;
        int p = nt >> 1, half = nt & 1;
        bp[(ks * 1536 + 0   + p * 32 + lane) * 2 + half] = hiv;
        bp[(ks * 1536 + 768 + p * 32 + lane) * 2 + half] = lov;
        return;
    }

    // ---- rowsum ----
    __shared__ float4 red[256];
    __shared__ float msgS[H_];
    const int b = bid;
    {
        int k4 = tid & 31, n0 = tid >> 5;
        const float4* p = (const float4*)(h + (size_t)b * N_ * H_) + k4;
        float4 s = make_float4(0.f, 0.f, 0.f, 0.f);
        #pragma unroll
        for (int j = 0; j < 16; j++) {
            float4 v = p[(size_t)(n0 + 8 * j) * 32];
            s.x += v.x; s.y += v.y; s.z += v.z; s.w += v.w;
        }
        red[tid] = s;
    }
    __syncthreads();
    #pragma unroll
    for (int off = 128; off >= 32; off >>= 1) {
        if (tid < off) {
            float4 a = red[tid], c = red[tid + off];
            a.x += c.x; a.y += c.y; a.z += c.z; a.w += c.w;
            red[tid] = a;
        }
        __syncthreads();
    }
    // red[0..31] = hs as float4 (k = 4*idx..4*idx+3) -> view as float[128]
    const float* hsS = (const float*)red;

    // ---- message = tanh(hs . Wm[k,:] + N*bm) ----
    if (tid < H_) {
        const float4* wr = (const float4*)(Wm + (size_t)tid * H_);
        float d = 0.f;
        #pragma unroll
        for (int j = 0; j < H_ / 4; j++) {
            float4 w = wr[j];
            d += hsS[4 * j + 0] * w.x + hsS[4 * j + 1] * w.y
               + hsS[4 * j + 2] * w.z + hsS[4 * j + 3] * w.w;
        }
        msgS[tid] = tanhf(d + (float)N_ * bm[tid]);
    }
    __syncthreads();

    // ---- gate bias ----
    if (tid < H_) {
        #pragma unroll
        for (int q = 0; q < 3; q++) {
            int g = q * H_ + tid;
            const float4* wi = (const float4*)(Wih + (size_t)g * KX_);
            float d2 = 0.f;
            #pragma unroll
            for (int j = 0; j < H_ / 4; j++) {
                float4 w = wi[j];
                d2 += msgS[4 * j + 0] * w.x + msgS[4 * j + 1] * w.y
                    + msgS[4 * j + 2] * w.z + msgS[4 * j + 3] * w.w;
            }
            float bias = d2 + bih[g];
            if (g < 2 * H_) bias += bhh[g];
            g_bias[b * G3_ + g] = bias;
        }
    }
}

// ---------------- smem layout for k_main (bytes) ----------------
#define OFF_AH   0            //  9728  A_hi [32][152] bf16, 304B row stride
#define OFF_AL   9728         //  9728
#define OFF_JET  19456        //  1024  jets fp32 [32][8]
#define OFF_WJN  20480        //  4096  W_ih n-gate jets cols fp32 [128][8]
#define OFF_BIAS 24576        //  1536
#define OFF_BHHN 26112        //   512
#define SMEM_SZ  26624

// ---------------- main: 256 threads, 32 rows x 384 cols per CTA, 2 CTAs/SM ----------------
__global__ void __launch_bounds__(256, 2) k_main(
    const float* __restrict__ h, const float* __restrict__ jets,
    const float* __restrict__ Wih, const float* __restrict__ bhh,
    float* __restrict__ out)
{
    extern __shared__ char smem[];
    const int tid  = threadIdx.x;
    const int wn   = tid >> 5;          // 8 N-positions: 16 cols per gate each
    const int lane = tid & 31;
    const int cta  = blockIdx.x;        // 32 rows each, 4 CTAs per batch
    const int batch = cta >> 2;

    // ---- convert h -> A_hi / A_lo ----
    {
        const float4* hp = (const float4*)(h + (size_t)cta * 32 * 128);
        #pragma unroll
        for (int i = tid; i < 1024; i += 256) {
            int row = i >> 5, q = i & 31;
            float4 v = hp[i];
            uint2 hi2 = make_uint2(pack_bf2(v.x, v.y), pack_bf2(v.z, v.w));
            uint2 lo2 = make_uint2(pack_bf2_res(v.x, v.y), pack_bf2_res(v.z, v.w));
            *(uint2*)(smem + OFF_AH + row * 304 + q * 8) = hi2;
            *(uint2*)(smem + OFF_AL + row * 304 + q * 8) = lo2;
        }
    }
    // ---- jets cols (A K 128..151) + fp32 jets ----
    if (tid < 32) {
        int row = tid;
        const float4* jp = (const float4*)(jets + (size_t)(cta * 32 + row) * FE_);
        float4 j0 = jp[0], j1 = jp[1];
        *(float4*)(smem + OFF_JET + row * 32)      = j0;
        *(float4*)(smem + OFF_JET + row * 32 + 16) = j1;
        uint4 jh = make_uint4(pack_bf2(j0.x, j0.y), pack_bf2(j0.z, j0.w),
                              pack_bf2(j1.x, j1.y), pack_bf2(j1.z, j1.w));
        uint4 jl = make_uint4(pack_bf2_res(j0.x, j0.y), pack_bf2_res(j0.z, j0.w),
                              pack_bf2_res(j1.x, j1.y), pack_bf2_res(j1.z, j1.w));
        uint4 zz = make_uint4(0, 0, 0, 0);
        *(uint4*)(smem + OFF_AH + row * 304 + 256) = jh;
        *(uint4*)(smem + OFF_AH + row * 304 + 272) = zz;
        *(uint4*)(smem + OFF_AH + row * 304 + 288) = zz;
        *(uint4*)(smem + OFF_AL + row * 304 + 256) = jl;
        *(uint4*)(smem + OFF_AL + row * 304 + 272) = zz;
        *(uint4*)(smem + OFF_AL + row * 304 + 288) = zz;
    }
    // ---- W_ih n-gate jets cols, bias, bhh_n ----
    if (tid < 128) {
        const float4* wp = (const float4*)(Wih + (size_t)(2 * H_ + tid) * KX_ + H_);
        *(float4*)(smem + OFF_WJN + tid * 32)      = wp[0];
        *(float4*)(smem + OFF_WJN + tid * 32 + 16) = wp[1];
        ((float*)(smem + OFF_BHHN))[tid] = bhh[2 * H_ + tid];
    }
    for (int g = tid; g < G3_; g += 256)
        ((float*)(smem + OFF_BIAS))[g] = g_bias[batch * G3_ + g];
    __syncthreads();   // the ONLY barrier

    // acc[gate][mt][j][frag]
    float acc[3][2][2][4];
    #pragma unroll
    for (int g = 0; g < 3; g++)
        #pragma unroll
        for (int m = 0; m < 2; m++)
            #pragma unroll
            for (int j = 0; j < 2; j++) {
                acc[g][m][j][0] = 0.f; acc[g][m][j][1] = 0.f;
                acc[g][m][j][2] = 0.f; acc[g][m][j][3] = 0.f;
            }

    const uint32_t aRowOff = (uint32_t)(lane >> 2) * 304 + (lane & 3) * 4;
    const uint4* bBase = g_Bp + wn * 32 + lane;

    #pragma unroll
    for (int ks = 0; ks < KSTEPS; ks++) {
        // A fragments (hi + lo, 2 m-tiles) from smem
        uint32_t ah[2][4], al[2][4];
        #pragma unroll
        for (int mt = 0; mt < 2; mt++) {
            const char* pa = smem + OFF_AH + aRowOff + mt * 16 * 304 + ks * 32;
            const char* pl = smem + OFF_AL + aRowOff + mt * 16 * 304 + ks * 32;
            ah[mt][0] = *(const uint32_t*)(pa);
            ah[mt][1] = *(const uint32_t*)(pa + 2432);
            ah[mt][2] = *(const uint32_t*)(pa + 16);
            ah[mt][3] = *(const uint32_t*)(pa + 2448);
            al[mt][0] = *(const uint32_t*)(pl);
            al[mt][1] = *(const uint32_t*)(pl + 2432);
            al[mt][2] = *(const uint32_t*)(pl + 16);
            al[mt][3] = *(const uint32_t*)(pl + 2448);
        }
        // B fragments direct from global (L1/L2 resident, shared by all CTAs)
        const uint4* bp = bBase + ks * 1536;
        #pragma unroll
        for (int g = 0; g < 3; g++) {
            if (ks == KSTEPS - 1 && g == 2) continue;   // B_n rows 128..143 are zero
            uint4 bh = bp[g * 256];
            uint4 bl = bp[g * 256 + 768];
            #pragma unroll
            for (int mt = 0; mt < 2; mt++) {
                MMA16816(acc[g][mt][0], ah[mt][0], ah[mt][1], ah[mt][2], ah[mt][3], bh.x, bh.y);
                MMA16816(acc[g][mt][1], ah[mt][0], ah[mt][1], ah[mt][2], ah[mt][3], bh.z, bh.w);
                MMA16816(acc[g][mt][0], al[mt][0], al[mt][1], al[mt][2], al[mt][3], bh.x, bh.y);
                MMA16816(acc[g][mt][1], al[mt][0], al[mt][1], al[mt][2], al[mt][3], bh.z, bh.w);
                MMA16816(acc[g][mt][0], ah[mt][0], ah[mt][1], ah[mt][2], ah[mt][3], bl.x, bl.y);
                MMA16816(acc[g][mt][1], ah[mt][0], ah[mt][1], ah[mt][2], ah[mt][3], bl.z, bl.w);
            }
        }
    }

    // ---- GRU epilogue (warp-local, MUFU tanh) ----
    {
        const float* biasS = (const float*)(smem + OFF_BIAS);
        const float* bhhnS = (const float*)(smem + OFF_BHHN);
        const size_t mBase = (size_t)cta * 32;
        #pragma unroll
        for (int mt = 0; mt < 2; mt++) {
            #pragma unroll
            for (int half = 0; half < 2; half++) {
                const int row = mt * 16 + (lane >> 2) + half * 8;
                float4 ja = *(const float4*)(smem + OFF_JET + row * 32);
                float4 jb = *(const float4*)(smem + OFF_JET + row * 32 + 16);
                #pragma unroll
                for (int j = 0; j < 2; j++) {
                    const int c = wn * 16 + j * 8 + (lane & 3) * 2;
                    uint32_t hh = *(const uint32_t*)(smem + OFF_AH + row * 304 + c * 2);
                    uint32_t hl = *(const uint32_t*)(smem + OFF_AL + row * 304 + c * 2);
                    float o[2];
                    #pragma unroll
                    for (int e = 0; e < 2; e++) {
                        const int g = c + e;
                        const int fr = half * 2 + e;
                        float aR = acc[0][mt][j][fr];
                        float aZ = acc[1][mt][j][fr];
                        float aN = acc[2][mt][j][fr];
                        float4 wa = *(const float4*)(smem + OFF_WJN + g * 32);
                        float4 wb = *(const float4*)(smem + OFF_WJN + g * 32 + 16);
                        float jd = ja.x * wa.x + ja.y * wa.y + ja.z * wa.z + ja.w * wa.w
                                 + jb.x * wb.x + jb.y * wb.y + jb.z * wb.z + jb.w * wb.w;
                        float r = 0.5f * tanh_ap(0.5f * (aR + biasS[g])) + 0.5f;
                        float z = 0.5f * tanh_ap(0.5f * (aZ + biasS[128 + g])) + 0.5f;
                        float n = tanh_ap(jd + biasS[256 + g] + r * (aN + bhhnS[g]));
                        float hv = (e ? bf_hi(hh) : bf_lo(hh)) + (e ? bf_hi(hl) : bf_lo(hl));
                        o[e] = (1.f - z) * n + z * hv;
                    }
                    *(float2*)(out + (mBase + row) * 128 + c) = make_float2(o[0], o[1]);
                }
            }
        }
    }
}

extern "C" void kernel_launch(void* const* d_in, const int* in_sizes, int n_in,
                              void* d_out, int out_size) {
    const float* h    = (const float*)d_in[0];
    const float* jets = (const float*)d_in[1];
    // d_in[2] = mask (unused)
    const float* Wm   = (const float*)d_in[3];
    const float* bm   = (const float*)d_in[4];
    const float* Wih  = (const float*)d_in[5];
    const float* Whh  = (const float*)d_in[6];
    const float* bih  = (const float*)d_in[7];
    const float* bhh  = (const float*)d_in[8];
    float* out = (float*)d_out;

    cudaFuncSetAttribute(k_main, cudaFuncAttributeMaxDynamicSharedMemorySize, SMEM_SZ);

    k_pre<<<B_ + 54, 256>>>(h, Whh, Wih, Wm, bm, bih, bhh);
    k_main<<<4 * B_, 256, SMEM_SZ>>>(h, jets, Wih, bhh, out);
}

// round 9
// speedup vs baseline: 2.5239x; 1.0656x over previous
#include <cuda_runtime.h>
#include <cuda_fp16.h>
#include <cstdint>

#define B_  1024
#define N_  128
#define H_  128
#define FE_ 8
#define G3_ 384
#define KX_ 136
#define KSTEPS 9         // K = 144 (128 h + 8 jets + 8 zero)

// ---------------- device scratch ----------------
__device__ __align__(16) float g_msg[B_ * H_];
__device__ __align__(16) float g_bias[B_ * G3_];
// B_hi in MMA-fragment order (fp16): [ks][pair p (24)][lane (32)] uint4
__device__ __align__(16) uint4 g_Bp[KSTEPS * 768];

__device__ __forceinline__ uint32_t pack_h2(float a, float b) {
    __half ah = __float2half_rn(a), bh = __float2half_rn(b);
    return (uint32_t)__half_as_ushort(ah) | ((uint32_t)__half_as_ushort(bh) << 16);
}
__device__ __forceinline__ uint32_t pack_h2_res(float a, float b) {
    __half ah = __float2half_rn(a), bh = __float2half_rn(b);
    float ar = a - __half2float(ah), br = b - __half2float(bh);
    return (uint32_t)__half_as_ushort(__float2half_rn(ar))
         | ((uint32_t)__half_as_ushort(__float2half_rn(br)) << 16);
}
__device__ __forceinline__ float hf_lo(uint32_t u) {
    return __half2float(__ushort_as_half((unsigned short)(u & 0xffff)));
}
__device__ __forceinline__ float hf_hi(uint32_t u) {
    return __half2float(__ushort_as_half((unsigned short)(u >> 16)));
}
__device__ __forceinline__ float tanh_ap(float x) {
    float y;
    asm("tanh.approx.f32 %0, %1;" : "=f"(y) : "f"(x));
    return y;
}

#define MMA16816(ac, a0, a1, a2, a3, b0, b1)                                   \
    asm volatile("mma.sync.aligned.m16n8k16.row.col.f32.f16.f16.f32 "          \
                 "{%0,%1,%2,%3}, {%4,%5,%6,%7}, {%8,%9}, {%0,%1,%2,%3};"       \
                 : "+f"((ac)[0]), "+f"((ac)[1]), "+f"((ac)[2]), "+f"((ac)[3])  \
                 : "r"(a0), "r"(a1), "r"(a2), "r"(a3), "r"(b0), "r"(b1))

// ---------------- k_pre1 ----------------
// blocks [0, B_): rowsum -> message (tanh) -> g_msg
// blocks [B_, B_+54): weight permute into fp16 fragment order
__global__ void __launch_bounds__(256) k_pre1(
    const float* __restrict__ h,
    const float* __restrict__ Whh, const float* __restrict__ Wih,
    const float* __restrict__ Wm, const float* __restrict__ bm)
{
    const int bid = blockIdx.x;
    const int tid = threadIdx.x;

    if (bid >= B_) {
        int i = (bid - B_) * 256 + tid;           // < 13824 = KSTEPS*1536
        int ks = i / 1536, rem = i % 1536;
        int nt = rem >> 5, lane = rem & 31;
        int n = nt * 8 + (lane >> 2);
        int k0 = ks * 16 + (lane & 3) * 2;
        float w[4];
        #pragma unroll
        for (int q = 0; q < 4; q++) {
            int k = k0 + (q >> 1) * 8 + (q & 1);
            float v = 0.f;
            if (k < H_) v = Whh[n * H_ + k];
            else if (k < H_ + FE_ && n < 2 * H_) v = Wih[(size_t)n * KX_ + k];
            w[q] = v;
        }
        uint2 hiv = make_uint2(pack_h2(w[0], w[1]), pack_h2(w[2], w[3]));
        uint2* bp = (uint2*)g_Bp;
        int p = nt >> 1, half = nt & 1;
        bp[(ks * 768 + p * 32 + lane) * 2 + half] = hiv;
        return;
    }

    __shared__ float4 red[256];
    const int b = bid;
    {
        int k4 = tid & 31, n0 = tid >> 5;
        const float4* p = (const float4*)(h + (size_t)b * N_ * H_) + k4;
        float4 s = make_float4(0.f, 0.f, 0.f, 0.f);
        #pragma unroll
        for (int j = 0; j < 16; j++) {
            float4 v = p[(size_t)(n0 + 8 * j) * 32];
            s.x += v.x; s.y += v.y; s.z += v.z; s.w += v.w;
        }
        red[tid] = s;
    }
    __syncthreads();
    #pragma unroll
    for (int off = 128; off >= 32; off >>= 1) {
        if (tid < off) {
            float4 a = red[tid], c = red[tid + off];
            a.x += c.x; a.y += c.y; a.z += c.z; a.w += c.w;
            red[tid] = a;
        }
        __syncthreads();
    }
    const float* hsS = (const float*)red;   // hs[128]

    if (tid < H_) {
        const float4* wr = (const float4*)(Wm + (size_t)tid * H_);
        float d = 0.f;
        #pragma unroll
        for (int j = 0; j < H_ / 4; j++) {
            float4 w = wr[j];
            d += hsS[4 * j + 0] * w.x + hsS[4 * j + 1] * w.y
               + hsS[4 * j + 2] * w.z + hsS[4 * j + 3] * w.w;
        }
        g_msg[b * H_ + tid] = tanhf(d + (float)N_ * bm[tid]);
    }
}

// ---------------- k_pre2: bias GEMM, 64 blocks x 16 batches ----------------
__global__ void __launch_bounds__(256) k_pre2(
    const float* __restrict__ Wih, const float* __restrict__ bih,
    const float* __restrict__ bhh)
{
    __shared__ float msgS[16 * H_];
    const int tid = threadIdx.x;
    const int b0 = blockIdx.x * 16;
    for (int i = tid; i < 16 * 32; i += 256)
        ((float4*)msgS)[i] = ((const float4*)(g_msg + (size_t)b0 * H_))[i];
    __syncthreads();

    for (int g = tid; g < G3_; g += 256) {
        const float4* wr = (const float4*)(Wih + (size_t)g * KX_);
        float acc[16];
        #pragma unroll
        for (int b = 0; b < 16; b++) acc[b] = 0.f;
        #pragma unroll 8
        for (int j = 0; j < H_ / 4; j++) {
            float4 w = wr[j];
            #pragma unroll
            for (int b = 0; b < 16; b++) {
                const float* m = msgS + b * H_ + 4 * j;
                acc[b] += m[0] * w.x + m[1] * w.y + m[2] * w.z + m[3] * w.w;
            }
        }
        float base = bih[g] + ((g < 2 * H_) ? bhh[g] : 0.f);
        #pragma unroll
        for (int b = 0; b < 16; b++)
            g_bias[(size_t)(b0 + b) * G3_ + g] = acc[b] + base;
    }
}

// ---------------- smem layout for k_main (bytes) ----------------
#define OFF_AH   0            //  9728  A_hi [32][152] fp16, 304B row stride
#define OFF_AL   9728         //  9728
#define OFF_JET  19456        //  1024  jets fp32 [32][8]
#define OFF_WJN  20480        //  4096  W_ih n-gate jets cols fp32 [128][8]
#define OFF_BIAS 24576        //  1536
#define OFF_BHHN 26112        //   512
#define SMEM_SZ  26624

// ---------------- main: 256 threads, 32 rows x 384 cols per CTA, 2 CTAs/SM ----------------
__global__ void __launch_bounds__(256, 2) k_main(
    const float* __restrict__ h, const float* __restrict__ jets,
    const float* __restrict__ Wih, const float* __restrict__ bhh,
    float* __restrict__ out)
{
    extern __shared__ char smem[];
    const int tid  = threadIdx.x;
    const int wn   = tid >> 5;          // 8 N-positions: 16 cols per gate each
    const int lane = tid & 31;
    const int cta  = blockIdx.x;        // 32 rows each, 4 CTAs per batch
    const int batch = cta >> 2;

    // ---- convert h -> A_hi / A_lo (fp16 + residual) ----
    {
        const float4* hp = (const float4*)(h + (size_t)cta * 32 * 128);
        #pragma unroll
        for (int i = tid; i < 1024; i += 256) {
            int row = i >> 5, q = i & 31;
            float4 v = hp[i];
            uint2 hi2 = make_uint2(pack_h2(v.x, v.y), pack_h2(v.z, v.w));
            uint2 lo2 = make_uint2(pack_h2_res(v.x, v.y), pack_h2_res(v.z, v.w));
            *(uint2*)(smem + OFF_AH + row * 304 + q * 8) = hi2;
            *(uint2*)(smem + OFF_AL + row * 304 + q * 8) = lo2;
        }
    }
    // ---- jets cols (A K 128..151) + fp32 jets ----
    if (tid < 32) {
        int row = tid;
        const float4* jp = (const float4*)(jets + (size_t)(cta * 32 + row) * FE_);
        float4 j0 = jp[0], j1 = jp[1];
        *(float4*)(smem + OFF_JET + row * 32)      = j0;
        *(float4*)(smem + OFF_JET + row * 32 + 16) = j1;
        uint4 jh = make_uint4(pack_h2(j0.x, j0.y), pack_h2(j0.z, j0.w),
                              pack_h2(j1.x, j1.y), pack_h2(j1.z, j1.w));
        uint4 jl = make_uint4(pack_h2_res(j0.x, j0.y), pack_h2_res(j0.z, j0.w),
                              pack_h2_res(j1.x, j1.y), pack_h2_res(j1.z, j1.w));
        uint4 zz = make_uint4(0, 0, 0, 0);
        *(uint4*)(smem + OFF_AH + row * 304 + 256) = jh;
        *(uint4*)(smem + OFF_AH + row * 304 + 272) = zz;
        *(uint4*)(smem + OFF_AH + row * 304 + 288) = zz;
        *(uint4*)(smem + OFF_AL + row * 304 + 256) = jl;
        *(uint4*)(smem + OFF_AL + row * 304 + 272) = zz;
        *(uint4*)(smem + OFF_AL + row * 304 + 288) = zz;
    }
    // ---- W_ih n-gate jets cols, bias, bhh_n ----
    if (tid < 128) {
        const float4* wp = (const float4*)(Wih + (size_t)(2 * H_ + tid) * KX_ + H_);
        *(float4*)(smem + OFF_WJN + tid * 32)      = wp[0];
        *(float4*)(smem + OFF_WJN + tid * 32 + 16) = wp[1];
        ((float*)(smem + OFF_BHHN))[tid] = bhh[2 * H_ + tid];
    }
    for (int g = tid; g < G3_; g += 256)
        ((float*)(smem + OFF_BIAS))[g] = g_bias[(size_t)batch * G3_ + g];
    __syncthreads();   // the ONLY barrier

    // acc[gate][mt][j][frag]
    float acc[3][2][2][4];
    #pragma unroll
    for (int g = 0; g < 3; g++)
        #pragma unroll
        for (int m = 0; m < 2; m++)
            #pragma unroll
            for (int j = 0; j < 2; j++) {
                acc[g][m][j][0] = 0.f; acc[g][m][j][1] = 0.f;
                acc[g][m][j][2] = 0.f; acc[g][m][j][3] = 0.f;
            }

    const uint32_t aRowOff = (uint32_t)(lane >> 2) * 304 + (lane & 3) * 4;
    const uint4* bBase = g_Bp + wn * 32 + lane;

    #pragma unroll
    for (int ks = 0; ks < KSTEPS; ks++) {
        // A fragments (hi + lo, 2 m-tiles) from smem
        uint32_t ah[2][4], al[2][4];
        #pragma unroll
        for (int mt = 0; mt < 2; mt++) {
            const char* pa = smem + OFF_AH + aRowOff + mt * 16 * 304 + ks * 32;
            const char* pl = smem + OFF_AL + aRowOff + mt * 16 * 304 + ks * 32;
            ah[mt][0] = *(const uint32_t*)(pa);
            ah[mt][1] = *(const uint32_t*)(pa + 2432);
            ah[mt][2] = *(const uint32_t*)(pa + 16);
            ah[mt][3] = *(const uint32_t*)(pa + 2448);
            al[mt][0] = *(const uint32_t*)(pl);
            al[mt][1] = *(const uint32_t*)(pl + 2432);
            al[mt][2] = *(const uint32_t*)(pl + 16);
            al[mt][3] = *(const uint32_t*)(pl + 2448);
        }
        // B_hi fragments direct from global (L1/L2 resident)
        const uint4* bp = bBase + ks * 768;
        #pragma unroll
        for (int g = 0; g < 3; g++) {
            if (ks == KSTEPS - 1 && g == 2) continue;   // B_n rows 128..143 are zero
            uint4 bh = bp[g * 256];
            #pragma unroll
            for (int mt = 0; mt < 2; mt++) {
                MMA16816(acc[g][mt][0], ah[mt][0], ah[mt][1], ah[mt][2], ah[mt][3], bh.x, bh.y);
                MMA16816(acc[g][mt][1], ah[mt][0], ah[mt][1], ah[mt][2], ah[mt][3], bh.z, bh.w);
                MMA16816(acc[g][mt][0], al[mt][0], al[mt][1], al[mt][2], al[mt][3], bh.x, bh.y);
                MMA16816(acc[g][mt][1], al[mt][0], al[mt][1], al[mt][2], al[mt][3], bh.z, bh.w);
            }
        }
    }

    // ---- GRU epilogue (warp-local, MUFU tanh) ----
    {
        const float* biasS = (const float*)(smem + OFF_BIAS);
        const float* bhhnS = (const float*)(smem + OFF_BHHN);
        const size_t mBase = (size_t)cta * 32;
        #pragma unroll
        for (int mt = 0; mt < 2; mt++) {
            #pragma unroll
            for (int half = 0; half < 2; half++) {
                const int row = mt * 16 + (lane >> 2) + half * 8;
                float4 ja = *(const float4*)(smem + OFF_JET + row * 32);
                float4 jb = *(const float4*)(smem + OFF_JET + row * 32 + 16);
                #pragma unroll
                for (int j = 0; j < 2; j++) {
                    const int c = wn * 16 + j * 8 + (lane & 3) * 2;
                    uint32_t hh = *(const uint32_t*)(smem + OFF_AH + row * 304 + c * 2);
                    uint32_t hl = *(const uint32_t*)(smem + OFF_AL + row * 304 + c * 2);
                    float o[2];
                    #pragma unroll
                    for (int e = 0; e < 2; e++) {
                        const int g = c + e;
                        const int fr = half * 2 + e;
                        float aR = acc[0][mt][j][fr];
                        float aZ = acc[1][mt][j][fr];
                        float aN = acc[2][mt][j][fr];
                        float4 wa = *(const float4*)(smem + OFF_WJN + g * 32);
                        float4 wb = *(const float4*)(smem + OFF_WJN + g * 32 + 16);
                        float jd = ja.x * wa.x + ja.y * wa.y + ja.z * wa.z + ja.w * wa.w
                                 + jb.x * wb.x + jb.y * wb.y + jb.z * wb.z + jb.w * wb.w;
                        float r = 0.5f * tanh_ap(0.5f * (aR + biasS[g])) + 0.5f;
                        float z = 0.5f * tanh_ap(0.5f * (aZ + biasS[128 + g])) + 0.5f;
                        float n = tanh_ap(jd + biasS[256 + g] + r * (aN + bhhnS[g]));
                        float hv = (e ? hf_hi(hh) : hf_lo(hh)) + (e ? hf_hi(hl) : hf_lo(hl));
                        o[e] = (1.f - z) * n + z * hv;
                    }
                    *(float2*)(out + (mBase + row) * 128 + c) = make_float2(o[0], o[1]);
                }
            }
        }
    }
}

extern "C" void kernel_launch(void* const* d_in, const int* in_sizes, int n_in,
                              void* d_out, int out_size) {
    const float* h    = (const float*)d_in[0];
    const float* jets = (const float*)d_in[1];
    // d_in[2] = mask (unused)
    const float* Wm   = (const float*)d_in[3];
    const float* bm   = (const float*)d_in[4];
    const float* Wih  = (const float*)d_in[5];
    const float* Whh  = (const float*)d_in[6];
    const float* bih  = (const float*)d_in[7];
    const float* bhh  = (const float*)d_in[8];
    float* out = (float*)d_out;

    cudaFuncSetAttribute(k_main, cudaFuncAttributeMaxDynamicSharedMemorySize, SMEM_SZ);

    k_pre1<<<B_ + 54, 256>>>(h, Whh, Wih, Wm, bm);
    k_pre2<<<B_ / 16, 256>>>(Wih, bih, bhh);
    k_main<<<4 * B_, 256, SMEM_SZ>>>(h, jets, Wih, bhh, out);
}

// round 10
// speedup vs baseline: 3.3592x; 1.3310x over previous
#include <cuda_runtime.h>
#include <cuda_fp16.h>
#include <cstdint>

#define B_  1024
#define N_  128
#define H_  128
#define FE_ 8
#define G3_ 384
#define KX_ 136
#define KSTEPS 9         // K = 144 (128 h + 8 jets + 8 zero)

// ---------------- device scratch ----------------
__device__ __align__(16) float g_hs[B_ * H_];
__device__ __align__(16) float g_bias[B_ * G3_];
// B_hi in MMA-fragment order (fp16): [ks][pair p (24)][lane (32)] uint4
__device__ __align__(16) uint4 g_Bp[KSTEPS * 768];

__device__ __forceinline__ uint32_t pack_h2(float a, float b) {
    __half ah = __float2half_rn(a), bh = __float2half_rn(b);
    return (uint32_t)__half_as_ushort(ah) | ((uint32_t)__half_as_ushort(bh) << 16);
}
__device__ __forceinline__ uint32_t pack_h2_res(float a, float b) {
    __half ah = __float2half_rn(a), bh = __float2half_rn(b);
    float ar = a - __half2float(ah), br = b - __half2float(bh);
    return (uint32_t)__half_as_ushort(__float2half_rn(ar))
         | ((uint32_t)__half_as_ushort(__float2half_rn(br)) << 16);
}
__device__ __forceinline__ float hf_lo(uint32_t u) {
    return __half2float(__ushort_as_half((unsigned short)(u & 0xffff)));
}
__device__ __forceinline__ float hf_hi(uint32_t u) {
    return __half2float(__ushort_as_half((unsigned short)(u >> 16)));
}
__device__ __forceinline__ float tanh_ap(float x) {
    float y;
    asm("tanh.approx.f32 %0, %1;" : "=f"(y) : "f"(x));
    return y;
}

#define MMA16816(ac, a0, a1, a2, a3, b0, b1)                                   \
    asm volatile("mma.sync.aligned.m16n8k16.row.col.f32.f16.f16.f32 "          \
                 "{%0,%1,%2,%3}, {%4,%5,%6,%7}, {%8,%9}, {%0,%1,%2,%3};"       \
                 : "+f"((ac)[0]), "+f"((ac)[1]), "+f"((ac)[2]), "+f"((ac)[3])  \
                 : "r"(a0), "r"(a1), "r"(a2), "r"(a3), "r"(b0), "r"(b1))

// ---------------- k_pre1 ----------------
// blocks [0, B_): pure-bandwidth rowsum -> g_hs
// blocks [B_, B_+54): weight permute into fp16 fragment order
__global__ void __launch_bounds__(256) k_pre1(
    const float* __restrict__ h,
    const float* __restrict__ Whh, const float* __restrict__ Wih)
{
    const int bid = blockIdx.x;
    const int tid = threadIdx.x;

    if (bid >= B_) {
        int i = (bid - B_) * 256 + tid;           // < 13824 = KSTEPS*1536
        int ks = i / 1536, rem = i % 1536;
        int nt = rem >> 5, lane = rem & 31;
        int n = nt * 8 + (lane >> 2);
        int k0 = ks * 16 + (lane & 3) * 2;
        float w[4];
        #pragma unroll
        for (int q = 0; q < 4; q++) {
            int k = k0 + (q >> 1) * 8 + (q & 1);
            float v = 0.f;
            if (k < H_) v = Whh[n * H_ + k];
            else if (k < H_ + FE_ && n < 2 * H_) v = Wih[(size_t)n * KX_ + k];
            w[q] = v;
        }
        uint2 hiv = make_uint2(pack_h2(w[0], w[1]), pack_h2(w[2], w[3]));
        uint2* bp = (uint2*)g_Bp;
        int p = nt >> 1, half = nt & 1;
        bp[(ks * 768 + p * 32 + lane) * 2 + half] = hiv;
        return;
    }

    __shared__ float4 red[256];
    const int b = bid;
    {
        int k4 = tid & 31, n0 = tid >> 5;
        const float4* p = (const float4*)(h + (size_t)b * N_ * H_) + k4;
        float4 s = make_float4(0.f, 0.f, 0.f, 0.f);
        #pragma unroll
        for (int j = 0; j < 16; j++) {
            float4 v = p[(size_t)(n0 + 8 * j) * 32];
            s.x += v.x; s.y += v.y; s.z += v.z; s.w += v.w;
        }
        red[tid] = s;
    }
    __syncthreads();
    #pragma unroll
    for (int off = 128; off >= 32; off >>= 1) {
        if (tid < off) {
            float4 a = red[tid], c = red[tid + off];
            a.x += c.x; a.y += c.y; a.z += c.z; a.w += c.w;
            red[tid] = a;
        }
        __syncthreads();
    }
    if (tid < 32) ((float4*)g_hs)[b * 32 + tid] = red[tid];
}

// ---------------- k_pre2: message + bias, 64 blocks x 16 batches ----------------
__global__ void __launch_bounds__(256) k_pre2(
    const float* __restrict__ Wm, const float* __restrict__ bm,
    const float* __restrict__ Wih, const float* __restrict__ bih,
    const float* __restrict__ bhh)
{
    __shared__ float hsS[16 * H_];    // 8 KB
    __shared__ float msgS[16 * H_];   // 8 KB
    const int tid = threadIdx.x;
    const int b0 = blockIdx.x * 16;

    for (int i = tid; i < 16 * 32; i += 256)
        ((float4*)hsS)[i] = ((const float4*)(g_hs + (size_t)b0 * H_))[i];
    __syncthreads();

    // message: each thread handles gate-dim k for 8 batches
    {
        const int k   = tid & 127;
        const int bh8 = (tid >> 7) * 8;
        const float4* wr = (const float4*)(Wm + (size_t)k * H_);
        float acc[8];
        #pragma unroll
        for (int b = 0; b < 8; b++) acc[b] = 0.f;
        #pragma unroll 8
        for (int j = 0; j < H_ / 4; j++) {
            float4 w = wr[j];
            #pragma unroll
            for (int b = 0; b < 8; b++) {
                const float* m = hsS + (bh8 + b) * H_ + 4 * j;
                acc[b] += m[0] * w.x + m[1] * w.y + m[2] * w.z + m[3] * w.w;
            }
        }
        float bb = (float)N_ * bm[k];
        #pragma unroll
        for (int b = 0; b < 8; b++)
            msgS[(bh8 + b) * H_ + k] = tanhf(acc[b] + bb);
    }
    __syncthreads();

    // bias GEMM: g across threads, 16 batches per thread
    for (int g = tid; g < G3_; g += 256) {
        const float4* wr = (const float4*)(Wih + (size_t)g * KX_);
        float acc[16];
        #pragma unroll
        for (int b = 0; b < 16; b++) acc[b] = 0.f;
        #pragma unroll 8
        for (int j = 0; j < H_ / 4; j++) {
            float4 w = wr[j];
            #pragma unroll
            for (int b = 0; b < 16; b++) {
                const float* m = msgS + b * H_ + 4 * j;
                acc[b] += m[0] * w.x + m[1] * w.y + m[2] * w.z + m[3] * w.w;
            }
        }
        float base = bih[g] + ((g < 2 * H_) ? bhh[g] : 0.f);
        #pragma unroll
        for (int b = 0; b < 16; b++)
            g_bias[(size_t)(b0 + b) * G3_ + g] = acc[b] + base;
    }
}

// ---------------- smem layout for k_main (bytes) ----------------
#define OFF_AH   0            //  9728  A_hi [32][152] fp16, 304B row stride
#define OFF_AL   9728         //  9728  A_lo (epilogue h reconstruction only)
#define OFF_JET  19456        //  1024  jets fp32 [32][8]
#define OFF_WJN  20480        //  4096  W_ih n-gate jets cols fp32 [128][8]
#define OFF_BIAS 24576        //  1536
#define OFF_BHHN 26112        //   512
#define SMEM_SZ  26624

// ---------------- main: 256 threads, 32 rows x 384 cols per CTA, 2 CTAs/SM ----------------
__global__ void __launch_bounds__(256, 2) k_main(
    const float* __restrict__ h, const float* __restrict__ jets,
    const float* __restrict__ Wih, const float* __restrict__ bhh,
    float* __restrict__ out)
{
    extern __shared__ char smem[];
    const int tid  = threadIdx.x;
    const int wn   = tid >> 5;          // 8 N-positions: 16 cols per gate each
    const int lane = tid & 31;
    const int cta  = blockIdx.x;        // 32 rows each, 4 CTAs per batch
    const int batch = cta >> 2;

    // ---- convert h -> A_hi (MMA) / A_lo (epilogue reconstruction) ----
    {
        const float4* hp = (const float4*)(h + (size_t)cta * 32 * 128);
        #pragma unroll
        for (int i = tid; i < 1024; i += 256) {
            int row = i >> 5, q = i & 31;
            float4 v = hp[i];
            uint2 hi2 = make_uint2(pack_h2(v.x, v.y), pack_h2(v.z, v.w));
            uint2 lo2 = make_uint2(pack_h2_res(v.x, v.y), pack_h2_res(v.z, v.w));
            *(uint2*)(smem + OFF_AH + row * 304 + q * 8) = hi2;
            *(uint2*)(smem + OFF_AL + row * 304 + q * 8) = lo2;
        }
    }
    // ---- jets cols (A K 128..151) + fp32 jets ----
    if (tid < 32) {
        int row = tid;
        const float4* jp = (const float4*)(jets + (size_t)(cta * 32 + row) * FE_);
        float4 j0 = jp[0], j1 = jp[1];
        *(float4*)(smem + OFF_JET + row * 32)      = j0;
        *(float4*)(smem + OFF_JET + row * 32 + 16) = j1;
        uint4 jh = make_uint4(pack_h2(j0.x, j0.y), pack_h2(j0.z, j0.w),
                              pack_h2(j1.x, j1.y), pack_h2(j1.z, j1.w));
        uint4 zz = make_uint4(0, 0, 0, 0);
        *(uint4*)(smem + OFF_AH + row * 304 + 256) = jh;
        *(uint4*)(smem + OFF_AH + row * 304 + 272) = zz;
        *(uint4*)(smem + OFF_AH + row * 304 + 288) = zz;
    }
    // ---- W_ih n-gate jets cols, bias, bhh_n ----
    if (tid < 128) {
        const float4* wp = (const float4*)(Wih + (size_t)(2 * H_ + tid) * KX_ + H_);
        *(float4*)(smem + OFF_WJN + tid * 32)      = wp[0];
        *(float4*)(smem + OFF_WJN + tid * 32 + 16) = wp[1];
        ((float*)(smem + OFF_BHHN))[tid] = bhh[2 * H_ + tid];
    }
    for (int g = tid; g < G3_; g += 256)
        ((float*)(smem + OFF_BIAS))[g] = g_bias[(size_t)batch * G3_ + g];
    __syncthreads();   // the ONLY barrier

    // acc[gate][mt][j][frag]
    float acc[3][2][2][4];
    #pragma unroll
    for (int g = 0; g < 3; g++)
        #pragma unroll
        for (int m = 0; m < 2; m++)
            #pragma unroll
            for (int j = 0; j < 2; j++) {
                acc[g][m][j][0] = 0.f; acc[g][m][j][1] = 0.f;
                acc[g][m][j][2] = 0.f; acc[g][m][j][3] = 0.f;
            }

    const uint32_t aRowOff = (uint32_t)(lane >> 2) * 304 + (lane & 3) * 4;
    const uint4* bBase = g_Bp + wn * 32 + lane;

    #pragma unroll
    for (int ks = 0; ks < KSTEPS; ks++) {
        // A_hi fragments (2 m-tiles) from smem
        uint32_t ah[2][4];
        #pragma unroll
        for (int mt = 0; mt < 2; mt++) {
            const char* pa = smem + OFF_AH + aRowOff + mt * 16 * 304 + ks * 32;
            ah[mt][0] = *(const uint32_t*)(pa);
            ah[mt][1] = *(const uint32_t*)(pa + 2432);
            ah[mt][2] = *(const uint32_t*)(pa + 16);
            ah[mt][3] = *(const uint32_t*)(pa + 2448);
        }
        // B_hi fragments direct from global (L1/L2 resident)
        const uint4* bp = bBase + ks * 768;
        #pragma unroll
        for (int g = 0; g < 3; g++) {
            if (ks == KSTEPS - 1 && g == 2) continue;   // B_n rows 128..143 are zero
            uint4 bh = bp[g * 256];
            #pragma unroll
            for (int mt = 0; mt < 2; mt++) {
                MMA16816(acc[g][mt][0], ah[mt][0], ah[mt][1], ah[mt][2], ah[mt][3], bh.x, bh.y);
                MMA16816(acc[g][mt][1], ah[mt][0], ah[mt][1], ah[mt][2], ah[mt][3], bh.z, bh.w);
            }
        }
    }

    // ---- GRU epilogue (warp-local, MUFU tanh) ----
    {
        const float* biasS = (const float*)(smem + OFF_BIAS);
        const float* bhhnS = (const float*)(smem + OFF_BHHN);
        const size_t mBase = (size_t)cta * 32;
        #pragma unroll
        for (int mt = 0; mt < 2; mt++) {
            #pragma unroll
            for (int half = 0; half < 2; half++) {
                const int row = mt * 16 + (lane >> 2) + half * 8;
                float4 ja = *(const float4*)(smem + OFF_JET + row * 32);
                float4 jb = *(const float4*)(smem + OFF_JET + row * 32 + 16);
                #pragma unroll
                for (int j = 0; j < 2; j++) {
                    const int c = wn * 16 + j * 8 + (lane & 3) * 2;
                    uint32_t hh = *(const uint32_t*)(smem + OFF_AH + row * 304 + c * 2);
                    uint32_t hl = *(const uint32_t*)(smem + OFF_AL + row * 304 + c * 2);
                    float o[2];
                    #pragma unroll
                    for (int e = 0; e < 2; e++) {
                        const int g = c + e;
                        const int fr = half * 2 + e;
                        float aR = acc[0][mt][j][fr];
                        float aZ = acc[1][mt][j][fr];
                        float aN = acc[2][mt][j][fr];
                        float4 wa = *(const float4*)(smem + OFF_WJN + g * 32);
                        float4 wb = *(const float4*)(smem + OFF_WJN + g * 32 + 16);
                        float jd = ja.x * wa.x + ja.y * wa.y + ja.z * wa.z + ja.w * wa.w
                                 + jb.x * wb.x + jb.y * wb.y + jb.z * wb.z + jb.w * wb.w;
                        float r = 0.5f * tanh_ap(0.5f * (aR + biasS[g])) + 0.5f;
                        float z = 0.5f * tanh_ap(0.5f * (aZ + biasS[128 + g])) + 0.5f;
                        float n = tanh_ap(jd + biasS[256 + g] + r * (aN + bhhnS[g]));
                        float hv = (e ? hf_hi(hh) : hf_lo(hh)) + (e ? hf_hi(hl) : hf_lo(hl));
                        o[e] = (1.f - z) * n + z * hv;
                    }
                    *(float2*)(out + (mBase + row) * 128 + c) = make_float2(o[0], o[1]);
                }
            }
        }
    }
}

extern "C" void kernel_launch(void* const* d_in, const int* in_sizes, int n_in,
                              void* d_out, int out_size) {
    const float* h    = (const float*)d_in[0];
    const float* jets = (const float*)d_in[1];
    // d_in[2] = mask (unused)
    const float* Wm   = (const float*)d_in[3];
    const float* bm   = (const float*)d_in[4];
    const float* Wih  = (const float*)d_in[5];
    const float* Whh  = (const float*)d_in[6];
    const float* bih  = (const float*)d_in[7];
    const float* bhh  = (const float*)d_in[8];
    float* out = (float*)d_out;

    cudaFuncSetAttribute(k_main, cudaFuncAttributeMaxDynamicSharedMemorySize, SMEM_SZ);

    k_pre1<<<B_ + 54, 256>>>(h, Whh, Wih);
    k_pre2<<<B_ / 16, 256>>>(Wm, bm, Wih, bih, bhh);
    k_main<<<4 * B_, 256, SMEM_SZ>>>(h, jets, Wih, bhh, out);
}